// round 10
// baseline (speedup 1.0000x reference)
#include <cuda_runtime.h>
#include <cuda_bf16.h>
#include <math.h>
#include <stdint.h>

#define SQ 2048
#define DIM 2048
#define NH 16
#define HD 128
#define HID 5632

#define K2_DIM (3 * DIM)    // 6144
#define K2_HID (3 * HID)    // 16896
#define NCH_DIM 96          // K2_DIM/64
#define NCH_HID 264         // K2_HID/64

// tiled operand layout: A tile = 128 rows x 144B (72 bf16), B tile = 256 x 144B
#define ATILE 9216
#define BTILE 18432
#define ATILE_B 18432
#define BTILE_B 36864

__device__ __forceinline__ uint32_t smem_u32(const void* p) {
    uint32_t a;
    asm("{ .reg .u64 t; cvta.to.shared.u64 t, %1; cvt.u32.u64 %0, t; }" : "=r"(a) : "l"(p));
    return a;
}
__device__ __forceinline__ void bulkcp(uint32_t s, const void* g, uint32_t bytes, uint32_t mbar) {
    asm volatile(
        "cp.async.bulk.shared::cluster.global.mbarrier::complete_tx::bytes [%0], [%1], %2, [%3];"
        :: "r"(s), "l"(g), "r"(bytes), "r"(mbar) : "memory");
}
#define MBARRIER_INIT(addr, cnt) \
    asm volatile("mbarrier.init.shared.b64 [%0], %1;" :: "r"((uint32_t)(addr)), "r"((uint32_t)(cnt)) : "memory")
#define MBARRIER_ARRIVE(addr) \
    asm volatile("mbarrier.arrive.shared.b64 _, [%0];" :: "r"((uint32_t)(addr)) : "memory")
#define MBARRIER_EXPECT_TX(addr, tx) \
    asm volatile("mbarrier.arrive.expect_tx.shared.b64 _, [%0], %1;" :: "r"((uint32_t)(addr)), "r"((uint32_t)(tx)) : "memory")
#define MBARRIER_WAIT_PARITY(addr, parity) do { \
    uint32_t _mb = (uint32_t)(addr); \
    uint32_t _p = (uint32_t)(parity); \
    uint32_t _done; \
    asm volatile("{\n\t.reg .pred p;\n\t" \
        "mbarrier.try_wait.parity.acquire.cta.shared::cta.b64 p, [%1], %2;\n\t" \
        "selp.b32 %0, 1, 0, p;\n\t}" : "=r"(_done) : "r"(_mb), "r"(_p) : "memory"); \
    if (!_done) { \
        asm volatile("{\n\t.reg .pred P1;\n\t" \
            "WL_%=:\n\t" \
            "mbarrier.try_wait.parity.acquire.cta.shared::cta.b64 P1, [%0], %1, 0x989680;\n\t" \
            "@P1 bra.uni WD_%=;\n\t" \
            "bra.uni WL_%=;\n\t" \
            "WD_%=:\n\t}" :: "r"(_mb), "r"(_p) : "memory"); \
    } \
} while (0)

// ---------------- scratch ----------------
__device__ float g_q [SQ * DIM];
__device__ float g_k [SQ * DIM];
__device__ float g_v [SQ * DIM];
__device__ float g_h [SQ * DIM];

__device__ __nv_bfloat16 g_xnb[(SQ / 128) * NCH_DIM * ATILE];
__device__ __nv_bfloat16 g_aob[(SQ / 128) * NCH_DIM * ATILE];
__device__ __nv_bfloat16 g_hnb[(SQ / 128) * NCH_DIM * ATILE];
__device__ __nv_bfloat16 g_fgb[(SQ / 128) * NCH_HID * ATILE];
__device__ __nv_bfloat16 g_wqkvt[(3 * DIM / 256) * NCH_DIM * BTILE];
__device__ __nv_bfloat16 g_wot  [(DIM / 256) * NCH_DIM * BTILE];
__device__ __nv_bfloat16 g_w13t [(2 * HID / 256) * NCH_DIM * BTILE];   // interleaved w1/w3 128-col blocks
__device__ __nv_bfloat16 g_w2t  [(DIM / 256) * NCH_HID * BTILE];

__device__ __forceinline__ size_t tiledA_off(int m, int kx, int nch) {
    return (size_t)((m >> 7) * nch + (kx >> 6)) * ATILE + (m & 127) * 72 + (kx & 63);
}
__device__ __forceinline__ size_t tiledB_off(int n, int kx, int nch) {
    return (size_t)((n >> 8) * nch + (kx >> 6)) * BTILE + (n & 255) * 72 + (kx & 63);
}
// NOTE: the 3-element split group can straddle a 64-wide K-chunk boundary,
// so each element MUST be placed via its own tiled offset.
__device__ __forceinline__ void split3_store_A(float x, __nv_bfloat16* base, int m, int kx0, int nch) {
    __nv_bfloat16 hi = __float2bfloat16(x);
    __nv_bfloat16 lo = __float2bfloat16(x - __bfloat162float(hi));
    base[tiledA_off(m, kx0 + 0, nch)] = hi;   // {hi, lo, hi}
    base[tiledA_off(m, kx0 + 1, nch)] = lo;
    base[tiledA_off(m, kx0 + 2, nch)] = hi;
}
__device__ __forceinline__ void split3_store_B(float x, __nv_bfloat16* base, int n, int kx0, int nch) {
    __nv_bfloat16 hi = __float2bfloat16(x);
    __nv_bfloat16 lo = __float2bfloat16(x - __bfloat162float(hi));
    base[tiledB_off(n, kx0 + 0, nch)] = hi;   // {hi, hi, lo}
    base[tiledB_off(n, kx0 + 1, nch)] = hi;
    base[tiledB_off(n, kx0 + 2, nch)] = lo;
}

// ---------------- weight transpose + split (merged variants) ----------------
// Generic single weight: W[K,N] -> tiled Wt
__global__ void convert_w_t(const float* __restrict__ W, __nv_bfloat16* __restrict__ Wt,
                            int K, int N, int nch) {
    __shared__ float s[32][33];
    int k0 = blockIdx.x * 32, n0 = blockIdx.y * 32;
    int tx = threadIdx.x & 31, ty = threadIdx.x >> 5;
    #pragma unroll
    for (int r = 0; r < 4; r++) {
        int k = ty + r * 8;
        s[k][tx] = W[(size_t)(k0 + k) * N + n0 + tx];
    }
    __syncthreads();
    #pragma unroll
    for (int r = 0; r < 4; r++) {
        int n = ty + r * 8;
        split3_store_B(s[tx][n], Wt, n0 + n, 3 * (k0 + tx), nch);
    }
}

// merged wq/wk/wv: blockIdx.z selects weight; out offset z * (DIM/256)*NCH_DIM*BTILE
__global__ void convert_wqkv_t(const float* __restrict__ Wq, const float* __restrict__ Wk,
                               const float* __restrict__ Wv, __nv_bfloat16* __restrict__ Wt) {
    __shared__ float s[32][33];
    const float* W = (blockIdx.z == 0) ? Wq : ((blockIdx.z == 1) ? Wk : Wv);
    __nv_bfloat16* out = Wt + (size_t)blockIdx.z * (DIM / 256) * NCH_DIM * BTILE;
    int k0 = blockIdx.x * 32, n0 = blockIdx.y * 32;
    int tx = threadIdx.x & 31, ty = threadIdx.x >> 5;
    #pragma unroll
    for (int r = 0; r < 4; r++) {
        int k = ty + r * 8;
        s[k][tx] = W[(size_t)(k0 + k) * DIM + n0 + tx];
    }
    __syncthreads();
    #pragma unroll
    for (int r = 0; r < 4; r++) {
        int n = ty + r * 8;
        split3_store_B(s[tx][n], out, n0 + n, 3 * (k0 + tx), NCH_DIM);
    }
}

// merged w1/w3 interleaved: blockIdx.z = which; block pair j holds w1 cols then w3 cols
__global__ void convert_w13_t(const float* __restrict__ W1, const float* __restrict__ W3,
                              __nv_bfloat16* __restrict__ Wt) {
    __shared__ float s[32][33];
    int which = blockIdx.z;
    const float* W = which ? W3 : W1;
    int k0 = blockIdx.x * 32, n0 = blockIdx.y * 32;
    int tx = threadIdx.x & 31, ty = threadIdx.x >> 5;
    #pragma unroll
    for (int r = 0; r < 4; r++) {
        int k = ty + r * 8;
        s[k][tx] = W[(size_t)(k0 + k) * HID + n0 + tx];
    }
    __syncthreads();
    #pragma unroll
    for (int r = 0; r < 4; r++) {
        int n = n0 + ty + r * 8;
        int nn = ((n >> 7) << 8) + (which << 7) + (n & 127);
        split3_store_B(s[tx][ty + r * 8], Wt, nn, 3 * (k0 + tx), NCH_DIM);
    }
}

// ---------------- rmsnorm -> tiled split A ----------------
__global__ void rmsnorm_big_k(const float* __restrict__ x, const float* __restrict__ g,
                              __nv_bfloat16* __restrict__ o) {
    int row = blockIdx.x;
    const float* xr = x + (size_t)row * DIM;
    float ss = 0.f;
    for (int i = threadIdx.x; i < DIM; i += blockDim.x) { float v = xr[i]; ss += v * v; }
    __shared__ float red[32];
    int lane = threadIdx.x & 31, w = threadIdx.x >> 5;
    #pragma unroll
    for (int off = 16; off; off >>= 1) ss += __shfl_xor_sync(0xffffffffu, ss, off);
    if (lane == 0) red[w] = ss;
    __syncthreads();
    if (w == 0) {
        float v = (lane < (int)(blockDim.x >> 5)) ? red[lane] : 0.f;
        #pragma unroll
        for (int off = 16; off; off >>= 1) v += __shfl_xor_sync(0xffffffffu, v, off);
        if (lane == 0) red[0] = v;
    }
    __syncthreads();
    float inv = rsqrtf(red[0] / (float)DIM + 1e-6f);
    for (int i = threadIdx.x; i < DIM; i += blockDim.x)
        split3_store_A(g[i] * xr[i] * inv, o, row, 3 * i, NCH_DIM);
}

// ================= HMMA GEMM core =================
#define GBM 128
#define GBN 256
#define AROWB 144
#define STGB (ATILE_B + BTILE_B)
#define GNST 4
#define GPREF (GNST - 1)
#define HGEMM_SMEM (1024 + GNST * STGB)   // 222208

#define GEMM_PROLOG_AND_MAINLOOP()                                                       \
    extern __shared__ char sm[];                                                          \
    uint32_t sb = smem_u32(sm);                                                           \
    const uint32_t fullb = sb;                                                            \
    const uint32_t emptyb = sb + 64;                                                      \
    const uint32_t stage0 = sb + 1024;                                                    \
    const int tid = threadIdx.x;                                                          \
    const int wid = tid >> 5, lane = tid & 31;                                            \
    const int wm = (wid & 1) * 64;                                                        \
    const int wn = (wid >> 1) * 64;                                                       \
    if (tid == 0) {                                                                       \
        _Pragma("unroll")                                                                 \
        for (int s = 0; s < GNST; s++) {                                                  \
            MBARRIER_INIT(fullb + 8 * s, 1);                                              \
            MBARRIER_INIT(emptyb + 8 * s, 8);                                             \
        }                                                                                 \
    }                                                                                     \
    __syncthreads();                                                                      \
    float acc[4][8][4];                                                                   \
    _Pragma("unroll")                                                                     \
    for (int i = 0; i < 4; i++)                                                           \
        _Pragma("unroll")                                                                 \
        for (int j = 0; j < 8; j++)                                                       \
            _Pragma("unroll")                                                             \
            for (int r = 0; r < 4; r++) acc[i][j][r] = 0.f;                               \
    if (tid == 0) {                                                                       \
        _Pragma("unroll")                                                                 \
        for (int p = 0; p < GPREF; p++) {                                                 \
            if (p < nch) {                                                                \
                uint32_t fb = fullb + 8 * p;                                              \
                MBARRIER_EXPECT_TX(fb, STGB);                                             \
                bulkcp(stage0 + p * STGB, At + (size_t)p * ATILE, ATILE_B, fb);           \
                bulkcp(stage0 + p * STGB + ATILE_B, Bt + (size_t)p * BTILE, BTILE_B, fb); \
            }                                                                             \
        }                                                                                 \
    }                                                                                     \
    for (int c = 0; c < nch; c++) {                                                       \
        int s = c % GNST;                                                                 \
        if (tid == 0 && c + GPREF < nch) {                                                \
            int t2 = c + GPREF, s2 = t2 % GNST;                                           \
            if (t2 >= GNST) MBARRIER_WAIT_PARITY(emptyb + 8 * s2, ((t2 - GNST) / GNST) & 1); \
            uint32_t fb = fullb + 8 * s2;                                                 \
            MBARRIER_EXPECT_TX(fb, STGB);                                                 \
            bulkcp(stage0 + s2 * STGB, At + (size_t)t2 * ATILE, ATILE_B, fb);             \
            bulkcp(stage0 + s2 * STGB + ATILE_B, Bt + (size_t)t2 * BTILE, BTILE_B, fb);   \
        }                                                                                 \
        MBARRIER_WAIT_PARITY(fullb + 8 * s, (c / GNST) & 1);                              \
        uint32_t abase = stage0 + s * STGB;                                               \
        uint32_t bbase = abase + ATILE_B;                                                 \
        _Pragma("unroll")                                                                 \
        for (int ks = 0; ks < 4; ks++) {                                                  \
            uint32_t a[4][4];                                                             \
            _Pragma("unroll")                                                             \
            for (int i = 0; i < 4; i++) {                                                 \
                uint32_t addr = abase + (wm + i * 16 + (lane & 15)) * AROWB               \
                              + (ks * 2 + (lane >> 4)) * 16;                              \
                asm volatile("ldmatrix.sync.aligned.m8n8.x4.shared.b16 {%0,%1,%2,%3}, [%4];" \
                             : "=r"(a[i][0]), "=r"(a[i][1]), "=r"(a[i][2]), "=r"(a[i][3]) \
                             : "r"(addr));                                                \
            }                                                                             \
            uint32_t b[8][2];                                                             \
            _Pragma("unroll")                                                             \
            for (int j2 = 0; j2 < 4; j2++) {                                              \
                uint32_t addr = bbase                                                     \
                              + (wn + j2 * 16 + ((lane >> 4) & 1) * 8 + (lane & 7)) * AROWB \
                              + (ks * 2 + ((lane >> 3) & 1)) * 16;                        \
                asm volatile("ldmatrix.sync.aligned.m8n8.x4.shared.b16 {%0,%1,%2,%3}, [%4];" \
                             : "=r"(b[2 * j2][0]), "=r"(b[2 * j2][1]),                    \
                               "=r"(b[2 * j2 + 1][0]), "=r"(b[2 * j2 + 1][1])             \
                             : "r"(addr));                                                \
            }                                                                             \
            _Pragma("unroll")                                                             \
            for (int i = 0; i < 4; i++)                                                   \
                _Pragma("unroll")                                                         \
                for (int j = 0; j < 8; j++) {                                             \
                    asm volatile(                                                         \
                        "mma.sync.aligned.m16n8k16.row.col.f32.bf16.bf16.f32 "            \
                        "{%0,%1,%2,%3}, {%4,%5,%6,%7}, {%8,%9}, {%0,%1,%2,%3};"           \
                        : "+f"(acc[i][j][0]), "+f"(acc[i][j][1]),                         \
                          "+f"(acc[i][j][2]), "+f"(acc[i][j][3])                          \
                        : "r"(a[i][0]), "r"(a[i][1]), "r"(a[i][2]), "r"(a[i][3]),         \
                          "r"(b[j][0]), "r"(b[j][1]));                                    \
                }                                                                         \
        }                                                                                 \
        if (lane == 0) MBARRIER_ARRIVE(emptyb + 8 * s);                                   \
    }

// ---------------- generic GEMM with fp32 scatter epilogue ----------------
template <int RES>
__global__ __launch_bounds__(256, 1) void hgemm_k(
    const __nv_bfloat16* __restrict__ A, const __nv_bfloat16* __restrict__ B,
    const float* __restrict__ R,
    float* __restrict__ C0, float* __restrict__ C1, float* __restrict__ C2,
    int nblk_per, int Nout, int K2) {
    const int nch = K2 >> 6;
    const __nv_bfloat16* At = A + (size_t)blockIdx.y * nch * ATILE;
    const __nv_bfloat16* Bt = B + (size_t)blockIdx.x * nch * BTILE;
    GEMM_PROLOG_AND_MAINLOOP()

    int t = blockIdx.x / nblk_per;
    float* C = (t == 0) ? C0 : ((t == 1) ? C1 : C2);
    int n0 = (blockIdx.x % nblk_per) * GBN;
    int m0 = blockIdx.y * GBM;

    #pragma unroll
    for (int i = 0; i < 4; i++) {
        int row = m0 + wm + i * 16 + (lane >> 2);
        #pragma unroll
        for (int j = 0; j < 8; j++) {
            int col = n0 + wn + j * 8 + (lane & 3) * 2;
            size_t o0 = (size_t)row * Nout + col;
            size_t o1 = (size_t)(row + 8) * Nout + col;
            float2 v0 = make_float2(acc[i][j][0], acc[i][j][1]);
            float2 v1 = make_float2(acc[i][j][2], acc[i][j][3]);
            if (RES) {
                float2 r0 = *(const float2*)(R + o0);
                float2 r1 = *(const float2*)(R + o1);
                v0.x += r0.x; v0.y += r0.y;
                v1.x += r1.x; v1.y += r1.y;
            }
            *(float2*)(C + o0) = v0;
            *(float2*)(C + o1) = v1;
        }
    }
}

// ---------------- FFN-up GEMM with fused silu-gate epilogue ----------------
__global__ __launch_bounds__(256, 1) void hgemm_gate_k(
    const __nv_bfloat16* __restrict__ A, const __nv_bfloat16* __restrict__ B,
    __nv_bfloat16* __restrict__ G, int K2) {
    const int nch = K2 >> 6;
    const __nv_bfloat16* At = A + (size_t)blockIdx.y * nch * ATILE;
    const __nv_bfloat16* Bt = B + (size_t)blockIdx.x * nch * BTILE;
    GEMM_PROLOG_AND_MAINLOOP()

    __syncthreads();   // stage smem free for reuse
    const int FP = 132;
    float* fsm = (float*)(sm + 1024);

    if (wid >= 4) {    // f3 warps: wn 128/192 -> local col base wn-128
        int cb = wn - 128;
        #pragma unroll
        for (int i = 0; i < 4; i++) {
            int rl = wm + i * 16 + (lane >> 2);
            #pragma unroll
            for (int j = 0; j < 8; j++) {
                int col = cb + j * 8 + (lane & 3) * 2;
                fsm[rl * FP + col] = acc[i][j][0];
                fsm[rl * FP + col + 1] = acc[i][j][1];
                fsm[(rl + 8) * FP + col] = acc[i][j][2];
                fsm[(rl + 8) * FP + col + 1] = acc[i][j][3];
            }
        }
    }
    __syncthreads();
    if (wid < 4) {     // f1 warps: wn 0/64
        int m0 = blockIdx.y * GBM;
        int nb = blockIdx.x * 128;
        #pragma unroll
        for (int i = 0; i < 4; i++) {
            int rl = wm + i * 16 + (lane >> 2);
            #pragma unroll
            for (int j = 0; j < 8; j++) {
                int col = wn + j * 8 + (lane & 3) * 2;
                #pragma unroll
                for (int hh = 0; hh < 2; hh++) {
                    int r = rl + hh * 8;
                    float f1a = acc[i][j][2 * hh], f1b = acc[i][j][2 * hh + 1];
                    float f3a = fsm[r * FP + col], f3b = fsm[r * FP + col + 1];
                    float ga = f1a / (1.f + __expf(-f1a)) * f3a;
                    float gb = f1b / (1.f + __expf(-f1b)) * f3b;
                    split3_store_A(ga, G, m0 + r, 3 * (nb + col), NCH_HID);
                    split3_store_A(gb, G, m0 + r, 3 * (nb + col + 1), NCH_HID);
                }
            }
        }
    }
}

// ---------------- RoPE on q and k in-place ----------------
__global__ void rope_k(float* __restrict__ q, float* __restrict__ k,
                       const float* __restrict__ fc, const float* __restrict__ fs) {
    int i = blockIdx.x * blockDim.x + threadIdx.x;
    if (i >= SQ * NH * (HD / 2)) return;
    int p = i & 63;
    int h = (i >> 6) & (NH - 1);
    int s = i >> 10;
    float c = fc[s * 64 + p], sn = fs[s * 64 + p];
    size_t base = (size_t)s * DIM + h * HD + 2 * p;
    float2 qv = *(float2*)(q + base);
    float2 kv = *(float2*)(k + base);
    *(float2*)(q + base) = make_float2(qv.x * c - qv.y * sn, qv.x * sn + qv.y * c);
    *(float2*)(k + base) = make_float2(kv.x * c - kv.y * sn, kv.x * sn + kv.y * c);
}

// ---------------- causal flash attention (fp32) -> tiled split A ----------------
#define BQ 32
#define BKK 32
#define KPAD 132
#define SCPAD 33
#define ATTN_SMEM ((BQ * KPAD + 2 * BKK * KPAD + BQ * SCPAD) * 4)

__global__ __launch_bounds__(256) void attn_k(
    const float* __restrict__ q, const float* __restrict__ k,
    const float* __restrict__ v, __nv_bfloat16* __restrict__ ob) {
    extern __shared__ float smf[];
    float* Qs = smf;
    float* Ks = Qs + BQ * KPAD;
    float* Vs = Ks + BKK * KPAD;
    float* sc = Vs + BKK * KPAD;

    int tid = threadIdx.x;
    int h = blockIdx.y;
    int q0 = blockIdx.x * BQ;

    #pragma unroll
    for (int r = 0; r < 4; r++) {
        int idx = tid + 256 * r;
        int row = idx >> 5;
        int c4 = (idx & 31) << 2;
        *(float4*)(&Qs[row * KPAD + c4]) =
            *(const float4*)(q + (size_t)(q0 + row) * DIM + h * HD + c4);
    }

    int qr = tid >> 3;
    int kl = tid & 7;
    int qg = q0 + qr;

    float m = -INFINITY, l = 0.f;
    float4 acc4[4];
    #pragma unroll
    for (int ii = 0; ii < 4; ii++) acc4[ii] = make_float4(0.f, 0.f, 0.f, 0.f);

    const float scale = 0.08838834764831845f;
    int ntiles = blockIdx.x + 1;

    for (int t = 0; t < ntiles; t++) {
        int j0 = t * BKK;
        __syncthreads();
        #pragma unroll
        for (int r = 0; r < 4; r++) {
            int idx = tid + 256 * r;
            int row = idx >> 5;
            int c4 = (idx & 31) << 2;
            *(float4*)(&Ks[row * KPAD + c4]) =
                *(const float4*)(k + (size_t)(j0 + row) * DIM + h * HD + c4);
            *(float4*)(&Vs[row * KPAD + c4]) =
                *(const float4*)(v + (size_t)(j0 + row) * DIM + h * HD + c4);
        }
        __syncthreads();

        float s0 = 0.f, s1 = 0.f, s2 = 0.f, s3 = 0.f;
        #pragma unroll 8
        for (int d = 0; d < HD; d += 4) {
            float4 q4 = *(const float4*)(&Qs[qr * KPAD + d]);
            float4 k0v = *(const float4*)(&Ks[(kl + 0)  * KPAD + d]);
            float4 k1v = *(const float4*)(&Ks[(kl + 8)  * KPAD + d]);
            float4 k2v = *(const float4*)(&Ks[(kl + 16) * KPAD + d]);
            float4 k3v = *(const float4*)(&Ks[(kl + 24) * KPAD + d]);
            s0 += q4.x * k0v.x + q4.y * k0v.y + q4.z * k0v.z + q4.w * k0v.w;
            s1 += q4.x * k1v.x + q4.y * k1v.y + q4.z * k1v.z + q4.w * k1v.w;
            s2 += q4.x * k2v.x + q4.y * k2v.y + q4.z * k2v.z + q4.w * k2v.w;
            s3 += q4.x * k3v.x + q4.y * k3v.y + q4.z * k3v.z + q4.w * k3v.w;
        }
        float sv[4] = {s0, s1, s2, s3};
        #pragma unroll
        for (int i = 0; i < 4; i++) {
            int j = kl + 8 * i;
            float s = sv[i] * scale;
            if (j0 + j > qg) s = -INFINITY;
            sc[qr * SCPAD + j] = s;
        }
        __syncthreads();

        float tmax = -INFINITY;
        #pragma unroll 8
        for (int j = 0; j < BKK; j++) tmax = fmaxf(tmax, sc[qr * SCPAD + j]);
        float nm = fmaxf(m, tmax);
        float alpha = __expf(m - nm);
        __syncthreads();

        #pragma unroll
        for (int i = 0; i < 4; i++) {
            int j = kl + 8 * i;
            float s = sc[qr * SCPAD + j];
            sc[qr * SCPAD + j] = (s == -INFINITY) ? 0.f : __expf(s - nm);
        }
        __syncthreads();

        float ps = 0.f;
        #pragma unroll 8
        for (int j = 0; j < BKK; j++) ps += sc[qr * SCPAD + j];
        l = l * alpha + ps;
        m = nm;

        #pragma unroll
        for (int ii = 0; ii < 4; ii++) {
            acc4[ii].x *= alpha; acc4[ii].y *= alpha;
            acc4[ii].z *= alpha; acc4[ii].w *= alpha;
        }
        #pragma unroll 4
        for (int j = 0; j < BKK; j++) {
            float p = sc[qr * SCPAD + j];
            #pragma unroll
            for (int ii = 0; ii < 4; ii++) {
                float4 vv = *(const float4*)(&Vs[j * KPAD + kl * 4 + 32 * ii]);
                acc4[ii].x += p * vv.x; acc4[ii].y += p * vv.y;
                acc4[ii].z += p * vv.z; acc4[ii].w += p * vv.w;
            }
        }
    }

    float invl = 1.f / l;
    #pragma unroll
    for (int ii = 0; ii < 4; ii++) {
        float vals[4] = {acc4[ii].x * invl, acc4[ii].y * invl, acc4[ii].z * invl, acc4[ii].w * invl};
        #pragma unroll
        for (int c = 0; c < 4; c++) {
            int d = kl * 4 + 32 * ii + c;
            split3_store_A(vals[c], ob, qg, 3 * (h * HD + d), NCH_DIM);
        }
    }
}

// ---------------- launcher ----------------
extern "C" void kernel_launch(void* const* d_in, const int* in_sizes, int n_in,
                              void* d_out, int out_size) {
    const float* x  = (const float*)d_in[0];
    const float* fc = (const float*)d_in[1];
    const float* fs = (const float*)d_in[2];
    const float* wq = (const float*)d_in[4];
    const float* wk = (const float*)d_in[5];
    const float* wv = (const float*)d_in[6];
    const float* wo = (const float*)d_in[7];
    const float* w1 = (const float*)d_in[8];
    const float* w2 = (const float*)d_in[9];
    const float* w3 = (const float*)d_in[10];
    const float* ga = (const float*)d_in[11];
    const float* gf = (const float*)d_in[12];
    float* out = (float*)d_out;

    float *q, *k, *v, *h;
    __nv_bfloat16 *xnb, *aob, *hnb, *fgb, *wqkvt, *wot, *w13t, *w2t;
    cudaGetSymbolAddress((void**)&q,   g_q);
    cudaGetSymbolAddress((void**)&k,   g_k);
    cudaGetSymbolAddress((void**)&v,   g_v);
    cudaGetSymbolAddress((void**)&h,   g_h);
    cudaGetSymbolAddress((void**)&xnb, g_xnb);
    cudaGetSymbolAddress((void**)&aob, g_aob);
    cudaGetSymbolAddress((void**)&hnb, g_hnb);
    cudaGetSymbolAddress((void**)&fgb, g_fgb);
    cudaGetSymbolAddress((void**)&wqkvt, g_wqkvt);
    cudaGetSymbolAddress((void**)&wot,   g_wot);
    cudaGetSymbolAddress((void**)&w13t,  g_w13t);
    cudaGetSymbolAddress((void**)&w2t,   g_w2t);

    cudaFuncSetAttribute(attn_k, cudaFuncAttributeMaxDynamicSharedMemorySize, ATTN_SMEM);
    cudaFuncSetAttribute(hgemm_k<0>, cudaFuncAttributeMaxDynamicSharedMemorySize, HGEMM_SMEM);
    cudaFuncSetAttribute(hgemm_k<1>, cudaFuncAttributeMaxDynamicSharedMemorySize, HGEMM_SMEM);
    cudaFuncSetAttribute(hgemm_gate_k, cudaFuncAttributeMaxDynamicSharedMemorySize, HGEMM_SMEM);

    // ---- fork converters onto side stream (4 launches) ----
    cudaStream_t s2;
    cudaStreamCreate(&s2);
    cudaEvent_t eF, e1, e2, e3, e4;
    cudaEventCreateWithFlags(&eF, cudaEventDisableTiming);
    cudaEventCreateWithFlags(&e1, cudaEventDisableTiming);
    cudaEventCreateWithFlags(&e2, cudaEventDisableTiming);
    cudaEventCreateWithFlags(&e3, cudaEventDisableTiming);
    cudaEventCreateWithFlags(&e4, cudaEventDisableTiming);

    cudaEventRecord(eF, 0);
    cudaStreamWaitEvent(s2, eF, 0);

    convert_wqkv_t<<<dim3(DIM / 32, DIM / 32, 3), 256, 0, s2>>>(wq, wk, wv, wqkvt);
    cudaEventRecord(e1, s2);
    convert_w_t<<<dim3(DIM / 32, DIM / 32), 256, 0, s2>>>(wo, wot, DIM, DIM, NCH_DIM);
    cudaEventRecord(e2, s2);
    convert_w13_t<<<dim3(DIM / 32, HID / 32, 2), 256, 0, s2>>>(w1, w3, w13t);
    cudaEventRecord(e3, s2);
    convert_w_t<<<dim3(HID / 32, DIM / 32), 256, 0, s2>>>(w2, w2t, HID, DIM, NCH_HID);
    cudaEventRecord(e4, s2);

    // ---- main chain (launch #5 = rmsnorm, #6 = QKV hgemm -> ncu capture) ----
    rmsnorm_big_k<<<SQ, 256>>>(x, ga, xnb);

    cudaStreamWaitEvent(0, e1, 0);
    hgemm_k<0><<<dim3(3 * DIM / GBN, SQ / GBM), 256, HGEMM_SMEM>>>(
        xnb, wqkvt, nullptr, q, k, v, DIM / GBN, DIM, K2_DIM);

    rope_k<<<(SQ * NH * (HD / 2)) / 256, 256>>>(q, k, fc, fs);

    attn_k<<<dim3(SQ / BQ, NH), 256, ATTN_SMEM>>>(q, k, v, aob);

    cudaStreamWaitEvent(0, e2, 0);
    hgemm_k<1><<<dim3(DIM / GBN, SQ / GBM), 256, HGEMM_SMEM>>>(
        aob, wot, x, h, h, h, DIM / GBN, DIM, K2_DIM);

    rmsnorm_big_k<<<SQ, 256>>>(h, gf, hnb);

    cudaStreamWaitEvent(0, e3, 0);
    hgemm_gate_k<<<dim3(HID / 128, SQ / GBM), 256, HGEMM_SMEM>>>(hnb, w13t, fgb, K2_DIM);

    cudaStreamWaitEvent(0, e4, 0);
    hgemm_k<1><<<dim3(DIM / GBN, SQ / GBM), 256, HGEMM_SMEM>>>(
        fgb, w2t, h, out, out, out, DIM / GBN, DIM, K2_HID);
}

// round 15
// speedup vs baseline: 1.5453x; 1.5453x over previous
#include <cuda_runtime.h>
#include <cuda_bf16.h>
#include <math.h>
#include <stdint.h>

#define SQ 2048
#define DIM 2048
#define NH 16
#define HD 128
#define HID 5632

#define K2_DIM (3 * DIM)    // 6144
#define K2_HID (3 * HID)    // 16896
#define NCH_DIM 96          // K2_DIM/64
#define NCH_HID 264         // K2_HID/64

// tiled operand layout: A tile = 128 rows x 144B (72 bf16), B tile = 256 x 144B
#define ATILE 9216
#define BTILE 18432
#define ATILE_B 18432
#define BTILE_B 36864

__device__ __forceinline__ uint32_t smem_u32(const void* p) {
    uint32_t a;
    asm("{ .reg .u64 t; cvta.to.shared.u64 t, %1; cvt.u32.u64 %0, t; }" : "=r"(a) : "l"(p));
    return a;
}
__device__ __forceinline__ void bulkcp(uint32_t s, const void* g, uint32_t bytes, uint32_t mbar) {
    asm volatile(
        "cp.async.bulk.shared::cluster.global.mbarrier::complete_tx::bytes [%0], [%1], %2, [%3];"
        :: "r"(s), "l"(g), "r"(bytes), "r"(mbar) : "memory");
}
#define MBARRIER_INIT(addr, cnt) \
    asm volatile("mbarrier.init.shared.b64 [%0], %1;" :: "r"((uint32_t)(addr)), "r"((uint32_t)(cnt)) : "memory")
#define MBARRIER_ARRIVE(addr) \
    asm volatile("mbarrier.arrive.shared.b64 _, [%0];" :: "r"((uint32_t)(addr)) : "memory")
#define MBARRIER_EXPECT_TX(addr, tx) \
    asm volatile("mbarrier.arrive.expect_tx.shared.b64 _, [%0], %1;" :: "r"((uint32_t)(addr)), "r"((uint32_t)(tx)) : "memory")
#define MBARRIER_WAIT_PARITY(addr, parity) do { \
    uint32_t _mb = (uint32_t)(addr); \
    uint32_t _p = (uint32_t)(parity); \
    uint32_t _done; \
    asm volatile("{\n\t.reg .pred p;\n\t" \
        "mbarrier.try_wait.parity.acquire.cta.shared::cta.b64 p, [%1], %2;\n\t" \
        "selp.b32 %0, 1, 0, p;\n\t}" : "=r"(_done) : "r"(_mb), "r"(_p) : "memory"); \
    if (!_done) { \
        asm volatile("{\n\t.reg .pred P1;\n\t" \
            "WL_%=:\n\t" \
            "mbarrier.try_wait.parity.acquire.cta.shared::cta.b64 P1, [%0], %1, 0x989680;\n\t" \
            "@P1 bra.uni WD_%=;\n\t" \
            "bra.uni WL_%=;\n\t" \
            "WD_%=:\n\t}" :: "r"(_mb), "r"(_p) : "memory"); \
    } \
} while (0)

// ---------------- scratch ----------------
__device__ float g_q [SQ * DIM];
__device__ float g_k [SQ * DIM];
__device__ float g_v [SQ * DIM];
__device__ float g_h [SQ * DIM];

__device__ __nv_bfloat16 g_xnb[(SQ / 128) * NCH_DIM * ATILE];
__device__ __nv_bfloat16 g_aob[(SQ / 128) * NCH_DIM * ATILE];
__device__ __nv_bfloat16 g_hnb[(SQ / 128) * NCH_DIM * ATILE];
__device__ __nv_bfloat16 g_fgb[(SQ / 128) * NCH_HID * ATILE];
__device__ __nv_bfloat16 g_wqkvt[(3 * DIM / 256) * NCH_DIM * BTILE];
__device__ __nv_bfloat16 g_wot  [(DIM / 256) * NCH_DIM * BTILE];
__device__ __nv_bfloat16 g_w13t [(2 * HID / 256) * NCH_DIM * BTILE];   // interleaved w1/w3 128-col blocks
__device__ __nv_bfloat16 g_w2t  [(DIM / 256) * NCH_HID * BTILE];

__device__ __forceinline__ size_t tiledA_off(int m, int kx, int nch) {
    return (size_t)((m >> 7) * nch + (kx >> 6)) * ATILE + (m & 127) * 72 + (kx & 63);
}
__device__ __forceinline__ size_t tiledB_off(int n, int kx, int nch) {
    return (size_t)((n >> 8) * nch + (kx >> 6)) * BTILE + (n & 255) * 72 + (kx & 63);
}
// NOTE: the 3-element split group can straddle a 64-wide K-chunk boundary,
// so each element MUST be placed via its own tiled offset.
__device__ __forceinline__ void split3_store_A(float x, __nv_bfloat16* base, int m, int kx0, int nch) {
    __nv_bfloat16 hi = __float2bfloat16(x);
    __nv_bfloat16 lo = __float2bfloat16(x - __bfloat162float(hi));
    base[tiledA_off(m, kx0 + 0, nch)] = hi;   // {hi, lo, hi}
    base[tiledA_off(m, kx0 + 1, nch)] = lo;
    base[tiledA_off(m, kx0 + 2, nch)] = hi;
}
__device__ __forceinline__ void split3_store_B(float x, __nv_bfloat16* base, int n, int kx0, int nch) {
    __nv_bfloat16 hi = __float2bfloat16(x);
    __nv_bfloat16 lo = __float2bfloat16(x - __bfloat162float(hi));
    base[tiledB_off(n, kx0 + 0, nch)] = hi;   // {hi, hi, lo}
    base[tiledB_off(n, kx0 + 1, nch)] = hi;
    base[tiledB_off(n, kx0 + 2, nch)] = lo;
}

// ---------------- weight transpose + split (merged variants) ----------------
__global__ void convert_w_t(const float* __restrict__ W, __nv_bfloat16* __restrict__ Wt,
                            int K, int N, int nch) {
    __shared__ float s[32][33];
    int k0 = blockIdx.x * 32, n0 = blockIdx.y * 32;
    int tx = threadIdx.x & 31, ty = threadIdx.x >> 5;
    #pragma unroll
    for (int r = 0; r < 4; r++) {
        int k = ty + r * 8;
        s[k][tx] = W[(size_t)(k0 + k) * N + n0 + tx];
    }
    __syncthreads();
    #pragma unroll
    for (int r = 0; r < 4; r++) {
        int n = ty + r * 8;
        split3_store_B(s[tx][n], Wt, n0 + n, 3 * (k0 + tx), nch);
    }
}

// merged wq/wk/wv: blockIdx.z selects weight
__global__ void convert_wqkv_t(const float* __restrict__ Wq, const float* __restrict__ Wk,
                               const float* __restrict__ Wv, __nv_bfloat16* __restrict__ Wt) {
    __shared__ float s[32][33];
    const float* W = (blockIdx.z == 0) ? Wq : ((blockIdx.z == 1) ? Wk : Wv);
    __nv_bfloat16* out = Wt + (size_t)blockIdx.z * (DIM / 256) * NCH_DIM * BTILE;
    int k0 = blockIdx.x * 32, n0 = blockIdx.y * 32;
    int tx = threadIdx.x & 31, ty = threadIdx.x >> 5;
    #pragma unroll
    for (int r = 0; r < 4; r++) {
        int k = ty + r * 8;
        s[k][tx] = W[(size_t)(k0 + k) * DIM + n0 + tx];
    }
    __syncthreads();
    #pragma unroll
    for (int r = 0; r < 4; r++) {
        int n = ty + r * 8;
        split3_store_B(s[tx][n], out, n0 + n, 3 * (k0 + tx), NCH_DIM);
    }
}

// merged w1/w3 interleaved: blockIdx.z = which
__global__ void convert_w13_t(const float* __restrict__ W1, const float* __restrict__ W3,
                              __nv_bfloat16* __restrict__ Wt) {
    __shared__ float s[32][33];
    int which = blockIdx.z;
    const float* W = which ? W3 : W1;
    int k0 = blockIdx.x * 32, n0 = blockIdx.y * 32;
    int tx = threadIdx.x & 31, ty = threadIdx.x >> 5;
    #pragma unroll
    for (int r = 0; r < 4; r++) {
        int k = ty + r * 8;
        s[k][tx] = W[(size_t)(k0 + k) * HID + n0 + tx];
    }
    __syncthreads();
    #pragma unroll
    for (int r = 0; r < 4; r++) {
        int n = n0 + ty + r * 8;
        int nn = ((n >> 7) << 8) + (which << 7) + (n & 127);
        split3_store_B(s[tx][ty + r * 8], Wt, nn, 3 * (k0 + tx), NCH_DIM);
    }
}

// ---------------- rmsnorm -> tiled split A ----------------
__global__ void rmsnorm_big_k(const float* __restrict__ x, const float* __restrict__ g,
                              __nv_bfloat16* __restrict__ o) {
    int row = blockIdx.x;
    const float* xr = x + (size_t)row * DIM;
    float ss = 0.f;
    for (int i = threadIdx.x; i < DIM; i += blockDim.x) { float v = xr[i]; ss += v * v; }
    __shared__ float red[32];
    int lane = threadIdx.x & 31, w = threadIdx.x >> 5;
    #pragma unroll
    for (int off = 16; off; off >>= 1) ss += __shfl_xor_sync(0xffffffffu, ss, off);
    if (lane == 0) red[w] = ss;
    __syncthreads();
    if (w == 0) {
        float v = (lane < (int)(blockDim.x >> 5)) ? red[lane] : 0.f;
        #pragma unroll
        for (int off = 16; off; off >>= 1) v += __shfl_xor_sync(0xffffffffu, v, off);
        if (lane == 0) red[0] = v;
    }
    __syncthreads();
    float inv = rsqrtf(red[0] / (float)DIM + 1e-6f);
    for (int i = threadIdx.x; i < DIM; i += blockDim.x)
        split3_store_A(g[i] * xr[i] * inv, o, row, 3 * i, NCH_DIM);
}

// ================= HMMA GEMM core (r9-proven: 3 stages, prefetch 2) =================
#define GBM 128
#define GBN 256
#define AROWB 144
#define STGB (ATILE_B + BTILE_B)
#define GNST 3
#define HGEMM_SMEM (1024 + GNST * STGB)   // 166912

#define GEMM_PROLOG_AND_MAINLOOP()                                                       \
    extern __shared__ char sm[];                                                          \
    uint32_t sb = smem_u32(sm);                                                           \
    const uint32_t fullb = sb;                                                            \
    const uint32_t emptyb = sb + 24;                                                      \
    const uint32_t stage0 = sb + 1024;                                                    \
    const int tid = threadIdx.x;                                                          \
    const int wid = tid >> 5, lane = tid & 31;                                            \
    const int wm = (wid & 1) * 64;                                                        \
    const int wn = (wid >> 1) * 64;                                                       \
    if (tid == 0) {                                                                       \
        _Pragma("unroll")                                                                 \
        for (int s = 0; s < GNST; s++) {                                                  \
            MBARRIER_INIT(fullb + 8 * s, 1);                                              \
            MBARRIER_INIT(emptyb + 8 * s, 8);                                             \
        }                                                                                 \
    }                                                                                     \
    __syncthreads();                                                                      \
    float acc[4][8][4];                                                                   \
    _Pragma("unroll")                                                                     \
    for (int i = 0; i < 4; i++)                                                           \
        _Pragma("unroll")                                                                 \
        for (int j = 0; j < 8; j++)                                                       \
            _Pragma("unroll")                                                             \
            for (int r = 0; r < 4; r++) acc[i][j][r] = 0.f;                               \
    if (tid == 0) {                                                                       \
        _Pragma("unroll")                                                                 \
        for (int p = 0; p < 2; p++) {                                                     \
            uint32_t fb = fullb + 8 * p;                                                  \
            MBARRIER_EXPECT_TX(fb, STGB);                                                 \
            bulkcp(stage0 + p * STGB, At + (size_t)p * ATILE, ATILE_B, fb);               \
            bulkcp(stage0 + p * STGB + ATILE_B, Bt + (size_t)p * BTILE, BTILE_B, fb);     \
        }                                                                                 \
    }                                                                                     \
    for (int c = 0; c < nch; c++) {                                                       \
        int s = c % GNST;                                                                 \
        if (tid == 0 && c + 2 < nch) {                                                    \
            int t2 = c + 2, s2 = t2 % GNST;                                               \
            if (t2 >= GNST) MBARRIER_WAIT_PARITY(emptyb + 8 * s2, ((t2 - GNST) / GNST) & 1); \
            uint32_t fb = fullb + 8 * s2;                                                 \
            MBARRIER_EXPECT_TX(fb, STGB);                                                 \
            bulkcp(stage0 + s2 * STGB, At + (size_t)t2 * ATILE, ATILE_B, fb);             \
            bulkcp(stage0 + s2 * STGB + ATILE_B, Bt + (size_t)t2 * BTILE, BTILE_B, fb);   \
        }                                                                                 \
        MBARRIER_WAIT_PARITY(fullb + 8 * s, (c / GNST) & 1);                              \
        uint32_t abase = stage0 + s * STGB;                                               \
        uint32_t bbase = abase + ATILE_B;                                                 \
        _Pragma("unroll")                                                                 \
        for (int ks = 0; ks < 4; ks++) {                                                  \
            uint32_t a[4][4];                                                             \
            _Pragma("unroll")                                                             \
            for (int i = 0; i < 4; i++) {                                                 \
                uint32_t addr = abase + (wm + i * 16 + (lane & 15)) * AROWB               \
                              + (ks * 2 + (lane >> 4)) * 16;                              \
                asm volatile("ldmatrix.sync.aligned.m8n8.x4.shared.b16 {%0,%1,%2,%3}, [%4];" \
                             : "=r"(a[i][0]), "=r"(a[i][1]), "=r"(a[i][2]), "=r"(a[i][3]) \
                             : "r"(addr));                                                \
            }                                                                             \
            uint32_t b[8][2];                                                             \
            _Pragma("unroll")                                                             \
            for (int j2 = 0; j2 < 4; j2++) {                                              \
                uint32_t addr = bbase                                                     \
                              + (wn + j2 * 16 + ((lane >> 4) & 1) * 8 + (lane & 7)) * AROWB \
                              + (ks * 2 + ((lane >> 3) & 1)) * 16;                        \
                asm volatile("ldmatrix.sync.aligned.m8n8.x4.shared.b16 {%0,%1,%2,%3}, [%4];" \
                             : "=r"(b[2 * j2][0]), "=r"(b[2 * j2][1]),                    \
                               "=r"(b[2 * j2 + 1][0]), "=r"(b[2 * j2 + 1][1])             \
                             : "r"(addr));                                                \
            }                                                                             \
            _Pragma("unroll")                                                             \
            for (int i = 0; i < 4; i++)                                                   \
                _Pragma("unroll")                                                         \
                for (int j = 0; j < 8; j++) {                                             \
                    asm volatile(                                                         \
                        "mma.sync.aligned.m16n8k16.row.col.f32.bf16.bf16.f32 "            \
                        "{%0,%1,%2,%3}, {%4,%5,%6,%7}, {%8,%9}, {%0,%1,%2,%3};"           \
                        : "+f"(acc[i][j][0]), "+f"(acc[i][j][1]),                         \
                          "+f"(acc[i][j][2]), "+f"(acc[i][j][3])                          \
                        : "r"(a[i][0]), "r"(a[i][1]), "r"(a[i][2]), "r"(a[i][3]),         \
                          "r"(b[j][0]), "r"(b[j][1]));                                    \
                }                                                                         \
        }                                                                                 \
        if (lane == 0) MBARRIER_ARRIVE(emptyb + 8 * s);                                   \
    }

// ---------------- generic GEMM with fp32 scatter epilogue ----------------
template <int RES>
__global__ __launch_bounds__(256, 1) void hgemm_k(
    const __nv_bfloat16* __restrict__ A, const __nv_bfloat16* __restrict__ B,
    const float* __restrict__ R,
    float* __restrict__ C0, float* __restrict__ C1, float* __restrict__ C2,
    int nblk_per, int Nout, int K2) {
    const int nch = K2 >> 6;
    const __nv_bfloat16* At = A + (size_t)blockIdx.y * nch * ATILE;
    const __nv_bfloat16* Bt = B + (size_t)blockIdx.x * nch * BTILE;
    GEMM_PROLOG_AND_MAINLOOP()

    int t = blockIdx.x / nblk_per;
    float* C = (t == 0) ? C0 : ((t == 1) ? C1 : C2);
    int n0 = (blockIdx.x % nblk_per) * GBN;
    int m0 = blockIdx.y * GBM;

    #pragma unroll
    for (int i = 0; i < 4; i++) {
        int row = m0 + wm + i * 16 + (lane >> 2);
        #pragma unroll
        for (int j = 0; j < 8; j++) {
            int col = n0 + wn + j * 8 + (lane & 3) * 2;
            size_t o0 = (size_t)row * Nout + col;
            size_t o1 = (size_t)(row + 8) * Nout + col;
            float2 v0 = make_float2(acc[i][j][0], acc[i][j][1]);
            float2 v1 = make_float2(acc[i][j][2], acc[i][j][3]);
            if (RES) {
                float2 r0 = *(const float2*)(R + o0);
                float2 r1 = *(const float2*)(R + o1);
                v0.x += r0.x; v0.y += r0.y;
                v1.x += r1.x; v1.y += r1.y;
            }
            *(float2*)(C + o0) = v0;
            *(float2*)(C + o1) = v1;
        }
    }
}

// ---------------- FFN-up GEMM with fused silu-gate epilogue ----------------
__global__ __launch_bounds__(256, 1) void hgemm_gate_k(
    const __nv_bfloat16* __restrict__ A, const __nv_bfloat16* __restrict__ B,
    __nv_bfloat16* __restrict__ G, int K2) {
    const int nch = K2 >> 6;
    const __nv_bfloat16* At = A + (size_t)blockIdx.y * nch * ATILE;
    const __nv_bfloat16* Bt = B + (size_t)blockIdx.x * nch * BTILE;
    GEMM_PROLOG_AND_MAINLOOP()

    __syncthreads();   // stage smem free for reuse
    const int FP = 132;
    float* fsm = (float*)(sm + 1024);

    if (wid >= 4) {    // f3 warps: wn 128/192 -> local col base wn-128
        int cb = wn - 128;
        #pragma unroll
        for (int i = 0; i < 4; i++) {
            int rl = wm + i * 16 + (lane >> 2);
            #pragma unroll
            for (int j = 0; j < 8; j++) {
                int col = cb + j * 8 + (lane & 3) * 2;
                fsm[rl * FP + col] = acc[i][j][0];
                fsm[rl * FP + col + 1] = acc[i][j][1];
                fsm[(rl + 8) * FP + col] = acc[i][j][2];
                fsm[(rl + 8) * FP + col + 1] = acc[i][j][3];
            }
        }
    }
    __syncthreads();
    if (wid < 4) {     // f1 warps: wn 0/64
        int m0 = blockIdx.y * GBM;
        int nb = blockIdx.x * 128;
        #pragma unroll
        for (int i = 0; i < 4; i++) {
            int rl = wm + i * 16 + (lane >> 2);
            #pragma unroll
            for (int j = 0; j < 8; j++) {
                int col = wn + j * 8 + (lane & 3) * 2;
                #pragma unroll
                for (int hh = 0; hh < 2; hh++) {
                    int r = rl + hh * 8;
                    float f1a = acc[i][j][2 * hh], f1b = acc[i][j][2 * hh + 1];
                    float f3a = fsm[r * FP + col], f3b = fsm[r * FP + col + 1];
                    float ga = f1a / (1.f + __expf(-f1a)) * f3a;
                    float gb = f1b / (1.f + __expf(-f1b)) * f3b;
                    split3_store_A(ga, G, m0 + r, 3 * (nb + col), NCH_HID);
                    split3_store_A(gb, G, m0 + r, 3 * (nb + col + 1), NCH_HID);
                }
            }
        }
    }
}

// ---------------- RoPE on q and k in-place ----------------
__global__ void rope_k(float* __restrict__ q, float* __restrict__ k,
                       const float* __restrict__ fc, const float* __restrict__ fs) {
    int i = blockIdx.x * blockDim.x + threadIdx.x;
    if (i >= SQ * NH * (HD / 2)) return;
    int p = i & 63;
    int h = (i >> 6) & (NH - 1);
    int s = i >> 10;
    float c = fc[s * 64 + p], sn = fs[s * 64 + p];
    size_t base = (size_t)s * DIM + h * HD + 2 * p;
    float2 qv = *(float2*)(q + base);
    float2 kv = *(float2*)(k + base);
    *(float2*)(q + base) = make_float2(qv.x * c - qv.y * sn, qv.x * sn + qv.y * c);
    *(float2*)(k + base) = make_float2(kv.x * c - kv.y * sn, kv.x * sn + kv.y * c);
}

// ---------------- causal flash attention (fp32) -> tiled split A ----------------
#define BQ 32
#define BKK 32
#define KPAD 132
#define SCPAD 33
#define ATTN_SMEM ((BQ * KPAD + 2 * BKK * KPAD + BQ * SCPAD) * 4)

__global__ __launch_bounds__(256) void attn_k(
    const float* __restrict__ q, const float* __restrict__ k,
    const float* __restrict__ v, __nv_bfloat16* __restrict__ ob) {
    extern __shared__ float smf[];
    float* Qs = smf;
    float* Ks = Qs + BQ * KPAD;
    float* Vs = Ks + BKK * KPAD;
    float* sc = Vs + BKK * KPAD;

    int tid = threadIdx.x;
    int h = blockIdx.y;
    int q0 = blockIdx.x * BQ;

    #pragma unroll
    for (int r = 0; r < 4; r++) {
        int idx = tid + 256 * r;
        int row = idx >> 5;
        int c4 = (idx & 31) << 2;
        *(float4*)(&Qs[row * KPAD + c4]) =
            *(const float4*)(q + (size_t)(q0 + row) * DIM + h * HD + c4);
    }

    int qr = tid >> 3;
    int kl = tid & 7;
    int qg = q0 + qr;

    float m = -INFINITY, l = 0.f;
    float4 acc4[4];
    #pragma unroll
    for (int ii = 0; ii < 4; ii++) acc4[ii] = make_float4(0.f, 0.f, 0.f, 0.f);

    const float scale = 0.08838834764831845f;
    int ntiles = blockIdx.x + 1;

    for (int t = 0; t < ntiles; t++) {
        int j0 = t * BKK;
        __syncthreads();
        #pragma unroll
        for (int r = 0; r < 4; r++) {
            int idx = tid + 256 * r;
            int row = idx >> 5;
            int c4 = (idx & 31) << 2;
            *(float4*)(&Ks[row * KPAD + c4]) =
                *(const float4*)(k + (size_t)(j0 + row) * DIM + h * HD + c4);
            *(float4*)(&Vs[row * KPAD + c4]) =
                *(const float4*)(v + (size_t)(j0 + row) * DIM + h * HD + c4);
        }
        __syncthreads();

        float s0 = 0.f, s1 = 0.f, s2 = 0.f, s3 = 0.f;
        #pragma unroll 8
        for (int d = 0; d < HD; d += 4) {
            float4 q4 = *(const float4*)(&Qs[qr * KPAD + d]);
            float4 k0v = *(const float4*)(&Ks[(kl + 0)  * KPAD + d]);
            float4 k1v = *(const float4*)(&Ks[(kl + 8)  * KPAD + d]);
            float4 k2v = *(const float4*)(&Ks[(kl + 16) * KPAD + d]);
            float4 k3v = *(const float4*)(&Ks[(kl + 24) * KPAD + d]);
            s0 += q4.x * k0v.x + q4.y * k0v.y + q4.z * k0v.z + q4.w * k0v.w;
            s1 += q4.x * k1v.x + q4.y * k1v.y + q4.z * k1v.z + q4.w * k1v.w;
            s2 += q4.x * k2v.x + q4.y * k2v.y + q4.z * k2v.z + q4.w * k2v.w;
            s3 += q4.x * k3v.x + q4.y * k3v.y + q4.z * k3v.z + q4.w * k3v.w;
        }
        float sv[4] = {s0, s1, s2, s3};
        #pragma unroll
        for (int i = 0; i < 4; i++) {
            int j = kl + 8 * i;
            float s = sv[i] * scale;
            if (j0 + j > qg) s = -INFINITY;
            sc[qr * SCPAD + j] = s;
        }
        __syncthreads();

        float tmax = -INFINITY;
        #pragma unroll 8
        for (int j = 0; j < BKK; j++) tmax = fmaxf(tmax, sc[qr * SCPAD + j]);
        float nm = fmaxf(m, tmax);
        float alpha = __expf(m - nm);
        __syncthreads();

        #pragma unroll
        for (int i = 0; i < 4; i++) {
            int j = kl + 8 * i;
            float s = sc[qr * SCPAD + j];
            sc[qr * SCPAD + j] = (s == -INFINITY) ? 0.f : __expf(s - nm);
        }
        __syncthreads();

        float ps = 0.f;
        #pragma unroll 8
        for (int j = 0; j < BKK; j++) ps += sc[qr * SCPAD + j];
        l = l * alpha + ps;
        m = nm;

        #pragma unroll
        for (int ii = 0; ii < 4; ii++) {
            acc4[ii].x *= alpha; acc4[ii].y *= alpha;
            acc4[ii].z *= alpha; acc4[ii].w *= alpha;
        }
        #pragma unroll 4
        for (int j = 0; j < BKK; j++) {
            float p = sc[qr * SCPAD + j];
            #pragma unroll
            for (int ii = 0; ii < 4; ii++) {
                float4 vv = *(const float4*)(&Vs[j * KPAD + kl * 4 + 32 * ii]);
                acc4[ii].x += p * vv.x; acc4[ii].y += p * vv.y;
                acc4[ii].z += p * vv.z; acc4[ii].w += p * vv.w;
            }
        }
    }

    float invl = 1.f / l;
    #pragma unroll
    for (int ii = 0; ii < 4; ii++) {
        float vals[4] = {acc4[ii].x * invl, acc4[ii].y * invl, acc4[ii].z * invl, acc4[ii].w * invl};
        #pragma unroll
        for (int c = 0; c < 4; c++) {
            int d = kl * 4 + 32 * ii + c;
            split3_store_A(vals[c], ob, qg, 3 * (h * HD + d), NCH_DIM);
        }
    }
}

// ---------------- launcher: single-stream linear chain ----------------
extern "C" void kernel_launch(void* const* d_in, const int* in_sizes, int n_in,
                              void* d_out, int out_size) {
    const float* x  = (const float*)d_in[0];
    const float* fc = (const float*)d_in[1];
    const float* fs = (const float*)d_in[2];
    const float* wq = (const float*)d_in[4];
    const float* wk = (const float*)d_in[5];
    const float* wv = (const float*)d_in[6];
    const float* wo = (const float*)d_in[7];
    const float* w1 = (const float*)d_in[8];
    const float* w2 = (const float*)d_in[9];
    const float* w3 = (const float*)d_in[10];
    const float* ga = (const float*)d_in[11];
    const float* gf = (const float*)d_in[12];
    float* out = (float*)d_out;

    float *q, *k, *v, *h;
    __nv_bfloat16 *xnb, *aob, *hnb, *fgb, *wqkvt, *wot, *w13t, *w2t;
    cudaGetSymbolAddress((void**)&q,   g_q);
    cudaGetSymbolAddress((void**)&k,   g_k);
    cudaGetSymbolAddress((void**)&v,   g_v);
    cudaGetSymbolAddress((void**)&h,   g_h);
    cudaGetSymbolAddress((void**)&xnb, g_xnb);
    cudaGetSymbolAddress((void**)&aob, g_aob);
    cudaGetSymbolAddress((void**)&hnb, g_hnb);
    cudaGetSymbolAddress((void**)&fgb, g_fgb);
    cudaGetSymbolAddress((void**)&wqkvt, g_wqkvt);
    cudaGetSymbolAddress((void**)&wot,   g_wot);
    cudaGetSymbolAddress((void**)&w13t,  g_w13t);
    cudaGetSymbolAddress((void**)&w2t,   g_w2t);

    cudaFuncSetAttribute(attn_k, cudaFuncAttributeMaxDynamicSharedMemorySize, ATTN_SMEM);
    cudaFuncSetAttribute(hgemm_k<0>, cudaFuncAttributeMaxDynamicSharedMemorySize, HGEMM_SMEM);
    cudaFuncSetAttribute(hgemm_k<1>, cudaFuncAttributeMaxDynamicSharedMemorySize, HGEMM_SMEM);
    cudaFuncSetAttribute(hgemm_gate_k, cudaFuncAttributeMaxDynamicSharedMemorySize, HGEMM_SMEM);

    // weight conversions (sequential, default stream)
    convert_wqkv_t<<<dim3(DIM / 32, DIM / 32, 3), 256>>>(wq, wk, wv, wqkvt);
    convert_w_t<<<dim3(DIM / 32, DIM / 32), 256>>>(wo, wot, DIM, DIM, NCH_DIM);
    convert_w13_t<<<dim3(DIM / 32, HID / 32, 2), 256>>>(w1, w3, w13t);
    convert_w_t<<<dim3(HID / 32, DIM / 32), 256>>>(w2, w2t, HID, DIM, NCH_HID);

    // main chain
    rmsnorm_big_k<<<SQ, 256>>>(x, ga, xnb);

    hgemm_k<0><<<dim3(3 * DIM / GBN, SQ / GBM), 256, HGEMM_SMEM>>>(
        xnb, wqkvt, nullptr, q, k, v, DIM / GBN, DIM, K2_DIM);

    rope_k<<<(SQ * NH * (HD / 2)) / 256, 256>>>(q, k, fc, fs);

    attn_k<<<dim3(SQ / BQ, NH), 256, ATTN_SMEM>>>(q, k, v, aob);

    hgemm_k<1><<<dim3(DIM / GBN, SQ / GBM), 256, HGEMM_SMEM>>>(
        aob, wot, x, h, h, h, DIM / GBN, DIM, K2_DIM);

    rmsnorm_big_k<<<SQ, 256>>>(h, gf, hnb);

    hgemm_gate_k<<<dim3(HID / 128, SQ / GBM), 256, HGEMM_SMEM>>>(hnb, w13t, fgb, K2_DIM);

    hgemm_k<1><<<dim3(DIM / GBN, SQ / GBM), 256, HGEMM_SMEM>>>(
        fgb, w2t, h, out, out, out, DIM / GBN, DIM, K2_HID);
}

// round 16
// speedup vs baseline: 1.6323x; 1.0563x over previous
#include <cuda_runtime.h>
#include <cuda_bf16.h>
#include <math.h>
#include <stdint.h>

#define SQ 2048
#define DIM 2048
#define NH 16
#define HD 128
#define HID 5632

#define K2_DIM (3 * DIM)    // 6144
#define K2_HID (3 * HID)    // 16896
#define NCH_DIM 96          // K2_DIM/64
#define NCH_HID 264         // K2_HID/64

// tiled operand layout: A tile = 128 rows x 144B (72 bf16), B tile = 256 x 144B
#define ATILE 9216
#define BTILE 18432
#define ATILE_B 18432
#define BTILE_B 36864

__device__ __forceinline__ uint32_t smem_u32(const void* p) {
    uint32_t a;
    asm("{ .reg .u64 t; cvta.to.shared.u64 t, %1; cvt.u32.u64 %0, t; }" : "=r"(a) : "l"(p));
    return a;
}
__device__ __forceinline__ void bulkcp(uint32_t s, const void* g, uint32_t bytes, uint32_t mbar) {
    asm volatile(
        "cp.async.bulk.shared::cluster.global.mbarrier::complete_tx::bytes [%0], [%1], %2, [%3];"
        :: "r"(s), "l"(g), "r"(bytes), "r"(mbar) : "memory");
}
#define MBARRIER_INIT(addr, cnt) \
    asm volatile("mbarrier.init.shared.b64 [%0], %1;" :: "r"((uint32_t)(addr)), "r"((uint32_t)(cnt)) : "memory")
#define MBARRIER_ARRIVE(addr) \
    asm volatile("mbarrier.arrive.shared.b64 _, [%0];" :: "r"((uint32_t)(addr)) : "memory")
#define MBARRIER_EXPECT_TX(addr, tx) \
    asm volatile("mbarrier.arrive.expect_tx.shared.b64 _, [%0], %1;" :: "r"((uint32_t)(addr)), "r"((uint32_t)(tx)) : "memory")
#define MBARRIER_WAIT_PARITY(addr, parity) do { \
    uint32_t _mb = (uint32_t)(addr); \
    uint32_t _p = (uint32_t)(parity); \
    uint32_t _done; \
    asm volatile("{\n\t.reg .pred p;\n\t" \
        "mbarrier.try_wait.parity.acquire.cta.shared::cta.b64 p, [%1], %2;\n\t" \
        "selp.b32 %0, 1, 0, p;\n\t}" : "=r"(_done) : "r"(_mb), "r"(_p) : "memory"); \
    if (!_done) { \
        asm volatile("{\n\t.reg .pred P1;\n\t" \
            "WL_%=:\n\t" \
            "mbarrier.try_wait.parity.acquire.cta.shared::cta.b64 P1, [%0], %1, 0x989680;\n\t" \
            "@P1 bra.uni WD_%=;\n\t" \
            "bra.uni WL_%=;\n\t" \
            "WD_%=:\n\t}" :: "r"(_mb), "r"(_p) : "memory"); \
    } \
} while (0)

// ---------------- scratch ----------------
__device__ float g_q [SQ * DIM];
__device__ float g_k [SQ * DIM];
__device__ float g_v [SQ * DIM];
__device__ float g_h [SQ * DIM];

__device__ __nv_bfloat16 g_xnb[(SQ / 128) * NCH_DIM * ATILE];
__device__ __nv_bfloat16 g_aob[(SQ / 128) * NCH_DIM * ATILE];
__device__ __nv_bfloat16 g_hnb[(SQ / 128) * NCH_DIM * ATILE];
__device__ __nv_bfloat16 g_fgb[(SQ / 128) * NCH_HID * ATILE];
__device__ __nv_bfloat16 g_wqkvt[(3 * DIM / 256) * NCH_DIM * BTILE];
__device__ __nv_bfloat16 g_wot  [(DIM / 256) * NCH_DIM * BTILE];
__device__ __nv_bfloat16 g_w13t [(2 * HID / 256) * NCH_DIM * BTILE];   // interleaved w1/w3 128-col blocks
__device__ __nv_bfloat16 g_w2t  [(DIM / 256) * NCH_HID * BTILE];

__device__ __forceinline__ size_t tiledA_off(int m, int kx, int nch) {
    return (size_t)((m >> 7) * nch + (kx >> 6)) * ATILE + (m & 127) * 72 + (kx & 63);
}
__device__ __forceinline__ size_t tiledB_off(int n, int kx, int nch) {
    return (size_t)((n >> 8) * nch + (kx >> 6)) * BTILE + (n & 255) * 72 + (kx & 63);
}
// NOTE: the 3-element split group can straddle a 64-wide K-chunk boundary,
// so each element MUST be placed via its own tiled offset.
__device__ __forceinline__ void split3_store_A(float x, __nv_bfloat16* base, int m, int kx0, int nch) {
    __nv_bfloat16 hi = __float2bfloat16(x);
    __nv_bfloat16 lo = __float2bfloat16(x - __bfloat162float(hi));
    base[tiledA_off(m, kx0 + 0, nch)] = hi;   // {hi, lo, hi}
    base[tiledA_off(m, kx0 + 1, nch)] = lo;
    base[tiledA_off(m, kx0 + 2, nch)] = hi;
}
__device__ __forceinline__ void split3_store_B(float x, __nv_bfloat16* base, int n, int kx0, int nch) {
    __nv_bfloat16 hi = __float2bfloat16(x);
    __nv_bfloat16 lo = __float2bfloat16(x - __bfloat162float(hi));
    base[tiledB_off(n, kx0 + 0, nch)] = hi;   // {hi, hi, lo}
    base[tiledB_off(n, kx0 + 1, nch)] = hi;
    base[tiledB_off(n, kx0 + 2, nch)] = lo;
}

// ---------------- weight transpose + split (merged variants) ----------------
__global__ void convert_w_t(const float* __restrict__ W, __nv_bfloat16* __restrict__ Wt,
                            int K, int N, int nch) {
    __shared__ float s[32][33];
    int k0 = blockIdx.x * 32, n0 = blockIdx.y * 32;
    int tx = threadIdx.x & 31, ty = threadIdx.x >> 5;
    #pragma unroll
    for (int r = 0; r < 4; r++) {
        int k = ty + r * 8;
        s[k][tx] = W[(size_t)(k0 + k) * N + n0 + tx];
    }
    __syncthreads();
    #pragma unroll
    for (int r = 0; r < 4; r++) {
        int n = ty + r * 8;
        split3_store_B(s[tx][n], Wt, n0 + n, 3 * (k0 + tx), nch);
    }
}

// merged wq/wk/wv: blockIdx.z selects weight
__global__ void convert_wqkv_t(const float* __restrict__ Wq, const float* __restrict__ Wk,
                               const float* __restrict__ Wv, __nv_bfloat16* __restrict__ Wt) {
    __shared__ float s[32][33];
    const float* W = (blockIdx.z == 0) ? Wq : ((blockIdx.z == 1) ? Wk : Wv);
    __nv_bfloat16* out = Wt + (size_t)blockIdx.z * (DIM / 256) * NCH_DIM * BTILE;
    int k0 = blockIdx.x * 32, n0 = blockIdx.y * 32;
    int tx = threadIdx.x & 31, ty = threadIdx.x >> 5;
    #pragma unroll
    for (int r = 0; r < 4; r++) {
        int k = ty + r * 8;
        s[k][tx] = W[(size_t)(k0 + k) * DIM + n0 + tx];
    }
    __syncthreads();
    #pragma unroll
    for (int r = 0; r < 4; r++) {
        int n = ty + r * 8;
        split3_store_B(s[tx][n], out, n0 + n, 3 * (k0 + tx), NCH_DIM);
    }
}

// merged w1/w3 interleaved: blockIdx.z = which
__global__ void convert_w13_t(const float* __restrict__ W1, const float* __restrict__ W3,
                              __nv_bfloat16* __restrict__ Wt) {
    __shared__ float s[32][33];
    int which = blockIdx.z;
    const float* W = which ? W3 : W1;
    int k0 = blockIdx.x * 32, n0 = blockIdx.y * 32;
    int tx = threadIdx.x & 31, ty = threadIdx.x >> 5;
    #pragma unroll
    for (int r = 0; r < 4; r++) {
        int k = ty + r * 8;
        s[k][tx] = W[(size_t)(k0 + k) * HID + n0 + tx];
    }
    __syncthreads();
    #pragma unroll
    for (int r = 0; r < 4; r++) {
        int n = n0 + ty + r * 8;
        int nn = ((n >> 7) << 8) + (which << 7) + (n & 127);
        split3_store_B(s[tx][ty + r * 8], Wt, nn, 3 * (k0 + tx), NCH_DIM);
    }
}

// ---------------- rmsnorm -> tiled split A ----------------
__global__ void rmsnorm_big_k(const float* __restrict__ x, const float* __restrict__ g,
                              __nv_bfloat16* __restrict__ o) {
    int row = blockIdx.x;
    const float* xr = x + (size_t)row * DIM;
    float ss = 0.f;
    for (int i = threadIdx.x; i < DIM; i += blockDim.x) { float v = xr[i]; ss += v * v; }
    __shared__ float red[32];
    int lane = threadIdx.x & 31, w = threadIdx.x >> 5;
    #pragma unroll
    for (int off = 16; off; off >>= 1) ss += __shfl_xor_sync(0xffffffffu, ss, off);
    if (lane == 0) red[w] = ss;
    __syncthreads();
    if (w == 0) {
        float v = (lane < (int)(blockDim.x >> 5)) ? red[lane] : 0.f;
        #pragma unroll
        for (int off = 16; off; off >>= 1) v += __shfl_xor_sync(0xffffffffu, v, off);
        if (lane == 0) red[0] = v;
    }
    __syncthreads();
    float inv = rsqrtf(red[0] / (float)DIM + 1e-6f);
    for (int i = threadIdx.x; i < DIM; i += blockDim.x)
        split3_store_A(g[i] * xr[i] * inv, o, row, 3 * i, NCH_DIM);
}

// ================= HMMA GEMM core (r9-proven: 3 stages, prefetch 2) =================
#define GBM 128
#define GBN 256
#define AROWB 144
#define STGB (ATILE_B + BTILE_B)
#define GNST 3
#define HGEMM_SMEM (1024 + GNST * STGB)   // 166912

#define GEMM_PROLOG_AND_MAINLOOP()                                                       \
    extern __shared__ char sm[];                                                          \
    uint32_t sb = smem_u32(sm);                                                           \
    const uint32_t fullb = sb;                                                            \
    const uint32_t emptyb = sb + 24;                                                      \
    const uint32_t stage0 = sb + 1024;                                                    \
    const int tid = threadIdx.x;                                                          \
    const int wid = tid >> 5, lane = tid & 31;                                            \
    const int wm = (wid & 1) * 64;                                                        \
    const int wn = (wid >> 1) * 64;                                                       \
    if (tid == 0) {                                                                       \
        _Pragma("unroll")                                                                 \
        for (int s = 0; s < GNST; s++) {                                                  \
            MBARRIER_INIT(fullb + 8 * s, 1);                                              \
            MBARRIER_INIT(emptyb + 8 * s, 8);                                             \
        }                                                                                 \
    }                                                                                     \
    __syncthreads();                                                                      \
    float acc[4][8][4];                                                                   \
    _Pragma("unroll")                                                                     \
    for (int i = 0; i < 4; i++)                                                           \
        _Pragma("unroll")                                                                 \
        for (int j = 0; j < 8; j++)                                                       \
            _Pragma("unroll")                                                             \
            for (int r = 0; r < 4; r++) acc[i][j][r] = 0.f;                               \
    if (tid == 0) {                                                                       \
        _Pragma("unroll")                                                                 \
        for (int p = 0; p < 2; p++) {                                                     \
            uint32_t fb = fullb + 8 * p;                                                  \
            MBARRIER_EXPECT_TX(fb, STGB);                                                 \
            bulkcp(stage0 + p * STGB, At + (size_t)p * ATILE, ATILE_B, fb);               \
            bulkcp(stage0 + p * STGB + ATILE_B, Bt + (size_t)p * BTILE, BTILE_B, fb);     \
        }                                                                                 \
    }                                                                                     \
    for (int c = 0; c < nch; c++) {                                                       \
        int s = c % GNST;                                                                 \
        if (tid == 0 && c + 2 < nch) {                                                    \
            int t2 = c + 2, s2 = t2 % GNST;                                               \
            if (t2 >= GNST) MBARRIER_WAIT_PARITY(emptyb + 8 * s2, ((t2 - GNST) / GNST) & 1); \
            uint32_t fb = fullb + 8 * s2;                                                 \
            MBARRIER_EXPECT_TX(fb, STGB);                                                 \
            bulkcp(stage0 + s2 * STGB, At + (size_t)t2 * ATILE, ATILE_B, fb);             \
            bulkcp(stage0 + s2 * STGB + ATILE_B, Bt + (size_t)t2 * BTILE, BTILE_B, fb);   \
        }                                                                                 \
        MBARRIER_WAIT_PARITY(fullb + 8 * s, (c / GNST) & 1);                              \
        uint32_t abase = stage0 + s * STGB;                                               \
        uint32_t bbase = abase + ATILE_B;                                                 \
        _Pragma("unroll")                                                                 \
        for (int ks = 0; ks < 4; ks++) {                                                  \
            uint32_t a[4][4];                                                             \
            _Pragma("unroll")                                                             \
            for (int i = 0; i < 4; i++) {                                                 \
                uint32_t addr = abase + (wm + i * 16 + (lane & 15)) * AROWB               \
                              + (ks * 2 + (lane >> 4)) * 16;                              \
                asm volatile("ldmatrix.sync.aligned.m8n8.x4.shared.b16 {%0,%1,%2,%3}, [%4];" \
                             : "=r"(a[i][0]), "=r"(a[i][1]), "=r"(a[i][2]), "=r"(a[i][3]) \
                             : "r"(addr));                                                \
            }                                                                             \
            uint32_t b[8][2];                                                             \
            _Pragma("unroll")                                                             \
            for (int j2 = 0; j2 < 4; j2++) {                                              \
                uint32_t addr = bbase                                                     \
                              + (wn + j2 * 16 + ((lane >> 4) & 1) * 8 + (lane & 7)) * AROWB \
                              + (ks * 2 + ((lane >> 3) & 1)) * 16;                        \
                asm volatile("ldmatrix.sync.aligned.m8n8.x4.shared.b16 {%0,%1,%2,%3}, [%4];" \
                             : "=r"(b[2 * j2][0]), "=r"(b[2 * j2][1]),                    \
                               "=r"(b[2 * j2 + 1][0]), "=r"(b[2 * j2 + 1][1])             \
                             : "r"(addr));                                                \
            }                                                                             \
            _Pragma("unroll")                                                             \
            for (int i = 0; i < 4; i++)                                                   \
                _Pragma("unroll")                                                         \
                for (int j = 0; j < 8; j++) {                                             \
                    asm volatile(                                                         \
                        "mma.sync.aligned.m16n8k16.row.col.f32.bf16.bf16.f32 "            \
                        "{%0,%1,%2,%3}, {%4,%5,%6,%7}, {%8,%9}, {%0,%1,%2,%3};"           \
                        : "+f"(acc[i][j][0]), "+f"(acc[i][j][1]),                         \
                          "+f"(acc[i][j][2]), "+f"(acc[i][j][3])                          \
                        : "r"(a[i][0]), "r"(a[i][1]), "r"(a[i][2]), "r"(a[i][3]),         \
                          "r"(b[j][0]), "r"(b[j][1]));                                    \
                }                                                                         \
        }                                                                                 \
        if (lane == 0) MBARRIER_ARRIVE(emptyb + 8 * s);                                   \
    }

// ---------------- generic GEMM with fp32 scatter epilogue ----------------
template <int RES>
__global__ __launch_bounds__(256, 1) void hgemm_k(
    const __nv_bfloat16* __restrict__ A, const __nv_bfloat16* __restrict__ B,
    const float* __restrict__ R,
    float* __restrict__ C0, float* __restrict__ C1, float* __restrict__ C2,
    int nblk_per, int Nout, int K2) {
    const int nch = K2 >> 6;
    const __nv_bfloat16* At = A + (size_t)blockIdx.y * nch * ATILE;
    const __nv_bfloat16* Bt = B + (size_t)blockIdx.x * nch * BTILE;
    GEMM_PROLOG_AND_MAINLOOP()

    int t = blockIdx.x / nblk_per;
    float* C = (t == 0) ? C0 : ((t == 1) ? C1 : C2);
    int n0 = (blockIdx.x % nblk_per) * GBN;
    int m0 = blockIdx.y * GBM;

    #pragma unroll
    for (int i = 0; i < 4; i++) {
        int row = m0 + wm + i * 16 + (lane >> 2);
        #pragma unroll
        for (int j = 0; j < 8; j++) {
            int col = n0 + wn + j * 8 + (lane & 3) * 2;
            size_t o0 = (size_t)row * Nout + col;
            size_t o1 = (size_t)(row + 8) * Nout + col;
            float2 v0 = make_float2(acc[i][j][0], acc[i][j][1]);
            float2 v1 = make_float2(acc[i][j][2], acc[i][j][3]);
            if (RES) {
                float2 r0 = *(const float2*)(R + o0);
                float2 r1 = *(const float2*)(R + o1);
                v0.x += r0.x; v0.y += r0.y;
                v1.x += r1.x; v1.y += r1.y;
            }
            *(float2*)(C + o0) = v0;
            *(float2*)(C + o1) = v1;
        }
    }
}

// ---------------- FFN-up GEMM with fused silu-gate epilogue ----------------
__global__ __launch_bounds__(256, 1) void hgemm_gate_k(
    const __nv_bfloat16* __restrict__ A, const __nv_bfloat16* __restrict__ B,
    __nv_bfloat16* __restrict__ G, int K2) {
    const int nch = K2 >> 6;
    const __nv_bfloat16* At = A + (size_t)blockIdx.y * nch * ATILE;
    const __nv_bfloat16* Bt = B + (size_t)blockIdx.x * nch * BTILE;
    GEMM_PROLOG_AND_MAINLOOP()

    __syncthreads();   // stage smem free for reuse
    const int FP = 132;
    float* fsm = (float*)(sm + 1024);

    if (wid >= 4) {    // f3 warps: wn 128/192 -> local col base wn-128
        int cb = wn - 128;
        #pragma unroll
        for (int i = 0; i < 4; i++) {
            int rl = wm + i * 16 + (lane >> 2);
            #pragma unroll
            for (int j = 0; j < 8; j++) {
                int col = cb + j * 8 + (lane & 3) * 2;
                fsm[rl * FP + col] = acc[i][j][0];
                fsm[rl * FP + col + 1] = acc[i][j][1];
                fsm[(rl + 8) * FP + col] = acc[i][j][2];
                fsm[(rl + 8) * FP + col + 1] = acc[i][j][3];
            }
        }
    }
    __syncthreads();
    if (wid < 4) {     // f1 warps: wn 0/64
        int m0 = blockIdx.y * GBM;
        int nb = blockIdx.x * 128;
        #pragma unroll
        for (int i = 0; i < 4; i++) {
            int rl = wm + i * 16 + (lane >> 2);
            #pragma unroll
            for (int j = 0; j < 8; j++) {
                int col = wn + j * 8 + (lane & 3) * 2;
                #pragma unroll
                for (int hh = 0; hh < 2; hh++) {
                    int r = rl + hh * 8;
                    float f1a = acc[i][j][2 * hh], f1b = acc[i][j][2 * hh + 1];
                    float f3a = fsm[r * FP + col], f3b = fsm[r * FP + col + 1];
                    float ga = f1a / (1.f + __expf(-f1a)) * f3a;
                    float gb = f1b / (1.f + __expf(-f1b)) * f3b;
                    split3_store_A(ga, G, m0 + r, 3 * (nb + col), NCH_HID);
                    split3_store_A(gb, G, m0 + r, 3 * (nb + col + 1), NCH_HID);
                }
            }
        }
    }
}

// ---------------- RoPE on q and k in-place ----------------
__global__ void rope_k(float* __restrict__ q, float* __restrict__ k,
                       const float* __restrict__ fc, const float* __restrict__ fs) {
    int i = blockIdx.x * blockDim.x + threadIdx.x;
    if (i >= SQ * NH * (HD / 2)) return;
    int p = i & 63;
    int h = (i >> 6) & (NH - 1);
    int s = i >> 10;
    float c = fc[s * 64 + p], sn = fs[s * 64 + p];
    size_t base = (size_t)s * DIM + h * HD + 2 * p;
    float2 qv = *(float2*)(q + base);
    float2 kv = *(float2*)(k + base);
    *(float2*)(q + base) = make_float2(qv.x * c - qv.y * sn, qv.x * sn + qv.y * c);
    *(float2*)(k + base) = make_float2(kv.x * c - kv.y * sn, kv.x * sn + kv.y * c);
}

// ---------------- causal flash attention (fp32, BKK=64) -> tiled split A ----------------
#define BQ 32
#define BKK 64
#define KPAD 132
#define SCPAD 65
#define ATTN_SMEM ((BQ * KPAD + 2 * BKK * KPAD + BQ * SCPAD) * 4)

__global__ __launch_bounds__(256) void attn_k(
    const float* __restrict__ q, const float* __restrict__ k,
    const float* __restrict__ v, __nv_bfloat16* __restrict__ ob) {
    extern __shared__ float smf[];
    float* Qs = smf;
    float* Ks = Qs + BQ * KPAD;
    float* Vs = Ks + BKK * KPAD;
    float* sc = Vs + BKK * KPAD;

    int tid = threadIdx.x;
    int h = blockIdx.y;
    int q0 = blockIdx.x * BQ;

    #pragma unroll
    for (int r = 0; r < 4; r++) {
        int idx = tid + 256 * r;
        int row = idx >> 5;
        int c4 = (idx & 31) << 2;
        *(float4*)(&Qs[row * KPAD + c4]) =
            *(const float4*)(q + (size_t)(q0 + row) * DIM + h * HD + c4);
    }

    int qr = tid >> 3;       // query row (0..31)
    int kl = tid & 7;        // key lane within row group
    int qg = q0 + qr;

    float m = -INFINITY, l = 0.f;
    float4 acc4[4];
    #pragma unroll
    for (int ii = 0; ii < 4; ii++) acc4[ii] = make_float4(0.f, 0.f, 0.f, 0.f);

    const float scale = 0.08838834764831845f;
    int ntiles = (blockIdx.x >> 1) + 1;   // 64-key tiles covering keys <= q0+31

    for (int t = 0; t < ntiles; t++) {
        int j0 = t * BKK;
        __syncthreads();
        // load K,V: 64 rows x 32 float4 each = 2048 float4 per operand, 8/thread
        #pragma unroll
        for (int r = 0; r < 8; r++) {
            int idx = tid + 256 * r;
            int row = idx >> 5;
            int c4 = (idx & 31) << 2;
            *(float4*)(&Ks[row * KPAD + c4]) =
                *(const float4*)(k + (size_t)(j0 + row) * DIM + h * HD + c4);
            *(float4*)(&Vs[row * KPAD + c4]) =
                *(const float4*)(v + (size_t)(j0 + row) * DIM + h * HD + c4);
        }
        __syncthreads();

        // scores: 8 keys per thread, j = kl + 8*i  (i = 0..7)
        float sv[8];
        #pragma unroll
        for (int i = 0; i < 8; i++) sv[i] = 0.f;
        #pragma unroll 4
        for (int d = 0; d < HD; d += 4) {
            float4 q4 = *(const float4*)(&Qs[qr * KPAD + d]);
            #pragma unroll
            for (int i = 0; i < 8; i++) {
                float4 kv4 = *(const float4*)(&Ks[(kl + 8 * i) * KPAD + d]);
                sv[i] += q4.x * kv4.x + q4.y * kv4.y + q4.z * kv4.z + q4.w * kv4.w;
            }
        }
        #pragma unroll
        for (int i = 0; i < 8; i++) {
            int j = kl + 8 * i;
            float s = sv[i] * scale;
            if (j0 + j > qg) s = -INFINITY;
            sc[qr * SCPAD + j] = s;
        }
        __syncthreads();

        float tmax = -INFINITY;
        #pragma unroll 8
        for (int j = 0; j < BKK; j++) tmax = fmaxf(tmax, sc[qr * SCPAD + j]);
        float nm = fmaxf(m, tmax);
        float alpha = __expf(m - nm);
        __syncthreads();

        #pragma unroll
        for (int i = 0; i < 8; i++) {
            int j = kl + 8 * i;
            float s = sc[qr * SCPAD + j];
            sc[qr * SCPAD + j] = (s == -INFINITY) ? 0.f : __expf(s - nm);
        }
        __syncthreads();

        float ps = 0.f;
        #pragma unroll 8
        for (int j = 0; j < BKK; j++) ps += sc[qr * SCPAD + j];
        l = l * alpha + ps;
        m = nm;

        #pragma unroll
        for (int ii = 0; ii < 4; ii++) {
            acc4[ii].x *= alpha; acc4[ii].y *= alpha;
            acc4[ii].z *= alpha; acc4[ii].w *= alpha;
        }
        #pragma unroll 4
        for (int j = 0; j < BKK; j++) {
            float p = sc[qr * SCPAD + j];
            #pragma unroll
            for (int ii = 0; ii < 4; ii++) {
                float4 vv = *(const float4*)(&Vs[j * KPAD + kl * 4 + 32 * ii]);
                acc4[ii].x += p * vv.x; acc4[ii].y += p * vv.y;
                acc4[ii].z += p * vv.z; acc4[ii].w += p * vv.w;
            }
        }
    }

    float invl = 1.f / l;
    #pragma unroll
    for (int ii = 0; ii < 4; ii++) {
        float vals[4] = {acc4[ii].x * invl, acc4[ii].y * invl, acc4[ii].z * invl, acc4[ii].w * invl};
        #pragma unroll
        for (int c = 0; c < 4; c++) {
            int d = kl * 4 + 32 * ii + c;
            split3_store_A(vals[c], ob, qg, 3 * (h * HD + d), NCH_DIM);
        }
    }
}

// ---------------- launcher ----------------
extern "C" void kernel_launch(void* const* d_in, const int* in_sizes, int n_in,
                              void* d_out, int out_size) {
    const float* x  = (const float*)d_in[0];
    const float* fc = (const float*)d_in[1];
    const float* fs = (const float*)d_in[2];
    const float* wq = (const float*)d_in[4];
    const float* wk = (const float*)d_in[5];
    const float* wv = (const float*)d_in[6];
    const float* wo = (const float*)d_in[7];
    const float* w1 = (const float*)d_in[8];
    const float* w2 = (const float*)d_in[9];
    const float* w3 = (const float*)d_in[10];
    const float* ga = (const float*)d_in[11];
    const float* gf = (const float*)d_in[12];
    float* out = (float*)d_out;

    float *q, *k, *v, *h;
    __nv_bfloat16 *xnb, *aob, *hnb, *fgb, *wqkvt, *wot, *w13t, *w2t;
    cudaGetSymbolAddress((void**)&q,   g_q);
    cudaGetSymbolAddress((void**)&k,   g_k);
    cudaGetSymbolAddress((void**)&v,   g_v);
    cudaGetSymbolAddress((void**)&h,   g_h);
    cudaGetSymbolAddress((void**)&xnb, g_xnb);
    cudaGetSymbolAddress((void**)&aob, g_aob);
    cudaGetSymbolAddress((void**)&hnb, g_hnb);
    cudaGetSymbolAddress((void**)&fgb, g_fgb);
    cudaGetSymbolAddress((void**)&wqkvt, g_wqkvt);
    cudaGetSymbolAddress((void**)&wot,   g_wot);
    cudaGetSymbolAddress((void**)&w13t,  g_w13t);
    cudaGetSymbolAddress((void**)&w2t,   g_w2t);

    cudaFuncSetAttribute(attn_k, cudaFuncAttributeMaxDynamicSharedMemorySize, ATTN_SMEM);
    cudaFuncSetAttribute(hgemm_k<0>, cudaFuncAttributeMaxDynamicSharedMemorySize, HGEMM_SMEM);
    cudaFuncSetAttribute(hgemm_k<1>, cudaFuncAttributeMaxDynamicSharedMemorySize, HGEMM_SMEM);
    cudaFuncSetAttribute(hgemm_gate_k, cudaFuncAttributeMaxDynamicSharedMemorySize, HGEMM_SMEM);

    // ---- fork converters onto side stream (measured -77us vs serial) ----
    cudaStream_t s2;
    cudaStreamCreate(&s2);
    cudaEvent_t eF, e1, e2, e3, e4;
    cudaEventCreateWithFlags(&eF, cudaEventDisableTiming);
    cudaEventCreateWithFlags(&e1, cudaEventDisableTiming);
    cudaEventCreateWithFlags(&e2, cudaEventDisableTiming);
    cudaEventCreateWithFlags(&e3, cudaEventDisableTiming);
    cudaEventCreateWithFlags(&e4, cudaEventDisableTiming);

    cudaEventRecord(eF, 0);
    cudaStreamWaitEvent(s2, eF, 0);

    convert_wqkv_t<<<dim3(DIM / 32, DIM / 32, 3), 256, 0, s2>>>(wq, wk, wv, wqkvt);
    cudaEventRecord(e1, s2);
    convert_w_t<<<dim3(DIM / 32, DIM / 32), 256, 0, s2>>>(wo, wot, DIM, DIM, NCH_DIM);
    cudaEventRecord(e2, s2);
    convert_w13_t<<<dim3(DIM / 32, HID / 32, 2), 256, 0, s2>>>(w1, w3, w13t);
    cudaEventRecord(e3, s2);
    convert_w_t<<<dim3(HID / 32, DIM / 32), 256, 0, s2>>>(w2, w2t, HID, DIM, NCH_HID);
    cudaEventRecord(e4, s2);

    // ---- main chain ----
    rmsnorm_big_k<<<SQ, 256>>>(x, ga, xnb);

    cudaStreamWaitEvent(0, e1, 0);
    hgemm_k<0><<<dim3(3 * DIM / GBN, SQ / GBM), 256, HGEMM_SMEM>>>(
        xnb, wqkvt, nullptr, q, k, v, DIM / GBN, DIM, K2_DIM);

    rope_k<<<(SQ * NH * (HD / 2)) / 256, 256>>>(q, k, fc, fs);

    attn_k<<<dim3(SQ / BQ, NH), 256, ATTN_SMEM>>>(q, k, v, aob);

    cudaStreamWaitEvent(0, e2, 0);
    hgemm_k<1><<<dim3(DIM / GBN, SQ / GBM), 256, HGEMM_SMEM>>>(
        aob, wot, x, h, h, h, DIM / GBN, DIM, K2_DIM);

    rmsnorm_big_k<<<SQ, 256>>>(h, gf, hnb);

    cudaStreamWaitEvent(0, e3, 0);
    hgemm_gate_k<<<dim3(HID / 128, SQ / GBM), 256, HGEMM_SMEM>>>(hnb, w13t, fgb, K2_DIM);

    cudaStreamWaitEvent(0, e4, 0);
    hgemm_k<1><<<dim3(DIM / GBN, SQ / GBM), 256, HGEMM_SMEM>>>(
        fgb, w2t, h, out, out, out, DIM / GBN, DIM, K2_HID);
}